// round 12
// baseline (speedup 1.0000x reference)
#include <cuda_runtime.h>
#include <cstdint>
#include <math.h>

#define Tn   1568
#define Dm   768
#define FFd  3072
#define NEx  8
#define HDh  64
#define KSP2 3          // split-K factor for FF2 (288 CTAs ~= one full wave)
#define STG  5          // cp.async pipeline stages (4 groups in flight)

// ---- scratch (allocation-free: __device__ globals) ----
__device__ float g_x1[Tn * Dm];            // residual after attention
__device__ float g_h2[Tn * Dm];            // LN2 output, tf32-rounded (MoE GEMM A)
__device__ float g_hbuf[Tn * FFd];         // FF1 activations, tf32-rounded, compact
__device__ float g_part[KSP2 * Tn * Dm];   // FF2 split-K partials
__device__ int   g_top1[Tn];
__device__ int   g_perm[Tn];
__device__ int   g_off[NEx + 1];

__device__ __forceinline__ unsigned f2tf32(float f) {
    unsigned r;
    asm("cvt.rna.tf32.f32 %0, %1;" : "=r"(r) : "f"(f));
    return r;
}

// ============================================================
// Kernel 1: LN1 + v-projection + residual + LN2 + gating
// Attention collapses algebraically: out_head(h) = v for all h.
// All 4 tokens processed CONCURRENTLY: thread -> (token tid>>6,
// lane tid&63, 12 elems). 5 barriers total (was ~20 serial).
// ============================================================
__global__ __launch_bounds__(256) void prep_kernel(
    const float* __restrict__ x,
    const float* __restrict__ ln1g, const float* __restrict__ ln1b,
    const float* __restrict__ Wv,   const float* __restrict__ bv,
    const float* __restrict__ ln2g, const float* __restrict__ ln2b,
    const float* __restrict__ Wg,   const float* __restrict__ bg)
{
    __shared__ float xs[4][Dm];
    __shared__ float hs[4][Dm];
    __shared__ float vs[4][HDh];
    __shared__ float red[16];       // red[w]=sum, red[8+w]=sumsq per warp

    const int tid  = threadIdx.x;
    const int t    = tid >> 6;      // token slot 0..3
    const int g    = tid & 63;      // lane within token
    const int w    = tid >> 5;      // warp 0..7 (token t = warps 2t, 2t+1)
    const int base = blockIdx.x * 4;
    const int tok  = base + t;

    // ---- LN1, all tokens parallel ----
    const float* xr = x + (size_t)tok * Dm;
    float lv[12];
    float s = 0.f, ss = 0.f;
    #pragma unroll
    for (int i = 0; i < 12; i++) {
        const int c = g + i * 64;
        float v = xr[c];
        lv[i] = v; xs[t][c] = v; s += v; ss += v * v;
    }
    #pragma unroll
    for (int o = 16; o; o >>= 1) {
        s  += __shfl_xor_sync(0xffffffffu, s,  o);
        ss += __shfl_xor_sync(0xffffffffu, ss, o);
    }
    if ((tid & 31) == 0) { red[w] = s; red[8 + w] = ss; }
    __syncthreads();
    s  = red[2 * t]     + red[2 * t + 1];
    ss = red[8 + 2 * t] + red[8 + 2 * t + 1];
    {
        float mu   = s * (1.f / Dm);
        float var  = ss * (1.f / Dm) - mu * mu;
        float rstd = rsqrtf(var + 1e-5f);
        #pragma unroll
        for (int i = 0; i < 12; i++) {
            const int c = g + i * 64;
            hs[t][c] = (lv[i] - mu) * rstd * ln1g[c] + ln1b[c];
        }
    }
    __syncthreads();

    // ---- v = LN1(x) @ Wv + bv : thread -> (token t, col g) ----
    {
        float a0 = 0.f, a1 = 0.f, a2 = 0.f, a3 = 0.f;
        #pragma unroll 4
        for (int k = 0; k < Dm; k += 4) {
            a0 += hs[t][k + 0] * Wv[(k + 0) * HDh + g];
            a1 += hs[t][k + 1] * Wv[(k + 1) * HDh + g];
            a2 += hs[t][k + 2] * Wv[(k + 2) * HDh + g];
            a3 += hs[t][k + 3] * Wv[(k + 3) * HDh + g];
        }
        vs[t][g] = (a0 + a1) + (a2 + a3) + bv[g];
    }
    __syncthreads();

    // ---- residual + LN2, all tokens parallel ----
    s = 0.f; ss = 0.f;
    #pragma unroll
    for (int i = 0; i < 12; i++) {
        const int c = g + i * 64;
        float v = xs[t][c] + vs[t][c & (HDh - 1)];
        lv[i] = v; s += v; ss += v * v;
        g_x1[(size_t)tok * Dm + c] = v;
    }
    #pragma unroll
    for (int o = 16; o; o >>= 1) {
        s  += __shfl_xor_sync(0xffffffffu, s,  o);
        ss += __shfl_xor_sync(0xffffffffu, ss, o);
    }
    if ((tid & 31) == 0) { red[w] = s; red[8 + w] = ss; }
    __syncthreads();
    s  = red[2 * t]     + red[2 * t + 1];
    ss = red[8 + 2 * t] + red[8 + 2 * t + 1];
    {
        float mu   = s * (1.f / Dm);
        float var  = ss * (1.f / Dm) - mu * mu;
        float rstd = rsqrtf(var + 1e-5f);
        #pragma unroll
        for (int i = 0; i < 12; i++) {
            const int c = g + i * 64;
            float h = (lv[i] - mu) * rstd * ln2g[c] + ln2b[c];
            hs[t][c] = h;                                            // fp32 for gating
            g_h2[(size_t)tok * Dm + c] = __uint_as_float(f2tf32(h)); // tf32-rna GEMM A
        }
    }
    __syncthreads();

    // ---- gate logits + argmax (fp32): warp wid handles token wid ----
    const int wid = tid >> 5, lane = tid & 31;
    if (wid < 4) {
        float lg[8];
        #pragma unroll
        for (int e = 0; e < 8; e++) lg[e] = 0.f;
        for (int k = lane; k < Dm; k += 32) {
            float h = hs[wid][k];
            #pragma unroll
            for (int e = 0; e < 8; e++) lg[e] += h * Wg[k * 8 + e];
        }
        #pragma unroll
        for (int e = 0; e < 8; e++)
            #pragma unroll
            for (int o = 16; o; o >>= 1) lg[e] += __shfl_xor_sync(0xffffffffu, lg[e], o);
        if (lane == 0) {
            float best = lg[0] + bg[0]; int bi = 0;
            #pragma unroll
            for (int e = 1; e < 8; e++) {
                float v = lg[e] + bg[e];
                if (v > best) { best = v; bi = e; }
            }
            g_top1[base + wid] = bi;
        }
    }
}

// ============================================================
// Kernel 2: bucket tokens by expert (single block, 1024 threads)
// ============================================================
__global__ __launch_bounds__(1024) void bucket_kernel()
{
    __shared__ int cnt[NEx];
    __shared__ int cur[NEx];
    const int tid = threadIdx.x;
    if (tid < NEx) cnt[tid] = 0;
    __syncthreads();
    for (int i = tid; i < Tn; i += 1024) atomicAdd(&cnt[g_top1[i]], 1);
    __syncthreads();
    if (tid == 0) {
        int acc = 0;
        for (int e = 0; e < NEx; e++) { g_off[e] = acc; cur[e] = acc; acc += cnt[e]; }
        g_off[NEx] = acc;
    }
    __syncthreads();
    for (int i = tid; i < Tn; i += 1024) {
        int e = g_top1[i];
        int p = atomicAdd(&cur[e], 1);
        g_perm[p] = i;
    }
}

__device__ __forceinline__ float gelu_exact(float v) { return v * normcdff(v); }

__device__ __forceinline__ void mma_tf32(float* c,
    unsigned a0, unsigned a1, unsigned a2, unsigned a3,
    unsigned b0, unsigned b1)
{
    asm volatile(
        "mma.sync.aligned.m16n8k8.row.col.f32.tf32.tf32.f32 "
        "{%0,%1,%2,%3}, {%4,%5,%6,%7}, {%8,%9}, {%0,%1,%2,%3};"
        : "+f"(c[0]), "+f"(c[1]), "+f"(c[2]), "+f"(c[3])
        : "r"(a0), "r"(a1), "r"(a2), "r"(a3), "r"(b0), "r"(b1));
}

__device__ __forceinline__ uint32_t smem_u32(const void* p) {
    return (uint32_t)__cvta_generic_to_shared(p);
}
__device__ __forceinline__ void cp16(uint32_t dst, const void* src) {
    asm volatile("cp.async.cg.shared.global [%0], [%1], 16;" :: "r"(dst), "l"(src));
}
__device__ __forceinline__ void cp16z(uint32_t dst, const void* src, int sz) {
    asm volatile("cp.async.cg.shared.global [%0], [%1], 16, %2;" :: "r"(dst), "l"(src), "r"(sz));
}

// ============================================================
// TF32 tensor-core MoE GEMM, cp.async 5-stage pipeline (4 groups in
// flight), BK=16, static stage indices via x5 unroll + static peel.
// Block tile 128x128, 8 warps of 32x64.  (UNCHANGED from round 11.)
// ============================================================
#define LDAA 20
#define LDBB 136
#define GEMM_SMEM_BYTES ((STG * 128 * LDAA + STG * 16 * LDBB) * 4)

template<int K, int N, bool IS_FF1, int KSPLIT>
__global__ __launch_bounds__(256, 2) void moe_gemm_cp(
    const float* __restrict__ W, const float* __restrict__ bias)
{
    const int e  = blockIdx.z / KSPLIT;
    const int kc = blockIdx.z % KSPLIT;
    constexpr int KS = K / KSPLIT;
    constexpr int NITER = KS / 16;
    static_assert(NITER >= STG, "pipeline deeper than loop");

    const int m0 = g_off[e];
    const int Me = g_off[e + 1] - m0;
    const int mt = blockIdx.y;
    if (mt * 128 >= Me) return;
    const int nt = blockIdx.x;

    extern __shared__ float smem[];
    float (*As)[128][LDAA] = (float (*)[128][LDAA])smem;
    float (*Bs)[16][LDBB]  = (float (*)[16][LDBB])(smem + STG * 128 * LDAA);

    const int tid  = threadIdx.x;
    const int lane = tid & 31;
    const int w    = tid >> 5;
    const int grp  = lane >> 2, tig = lane & 3;
    const int wrow = (w & 3) * 32;
    const int wcol = (w >> 2) * 64;

    const int ar0 = tid >> 2;            // A rows ar0, ar0+64
    const int akq = (tid & 3) * 4;       // A k-offset (floats)
    const int br0 = tid >> 5;            // B k-rows br0, br0+8
    const int bnq = (tid & 31) * 4;      // B n-offset (floats)

    const float* arowp[2]; int asz[2];
    #pragma unroll
    for (int i = 0; i < 2; i++) {
        int  mloc = mt * 128 + ar0 + i * 64;
        bool v    = mloc < Me;
        int  apos = m0 + (v ? mloc : 0);
        arowp[i] = (IS_FF1 ? &g_h2[(size_t)g_perm[apos] * K] : &g_hbuf[(size_t)apos * K])
                   + kc * KS + akq;
        asz[i] = v ? 16 : 0;
    }
    const float* __restrict__ Bbase =
        W + (size_t)e * K * N + (size_t)(kc * KS) * N + (size_t)nt * 128 + bnq;

    #define LOAD_STAGE(k0, st)                                                    \
        do {                                                                      \
            cp16z(smem_u32(&As[st][ar0][akq]),      arowp[0] + (k0), asz[0]);     \
            cp16z(smem_u32(&As[st][ar0 + 64][akq]), arowp[1] + (k0), asz[1]);     \
            cp16(smem_u32(&Bs[st][br0][bnq]),     Bbase + (size_t)((k0) + br0) * N);      \
            cp16(smem_u32(&Bs[st][br0 + 8][bnq]), Bbase + (size_t)((k0) + br0 + 8) * N);  \
            asm volatile("cp.async.commit_group;");                               \
        } while (0)

    float acc[2][8][4];
    #pragma unroll
    for (int i = 0; i < 2; i++)
        #pragma unroll
        for (int j = 0; j < 8; j++)
            #pragma unroll
            for (int r = 0; r < 4; r++) acc[i][j][r] = 0.f;

    #define ITER_BODY(st, kit)                                                        \
        do {                                                                          \
            if ((kit) + STG - 1 < NITER) {                                            \
                LOAD_STAGE(((kit) + STG - 1) * 16, ((st) + STG - 1) % STG);           \
            } else {                                                                  \
                asm volatile("cp.async.commit_group;");                               \
            }                                                                         \
            _Pragma("unroll")                                                         \
            for (int ks = 0; ks < 2; ks++) {                                          \
                const int kk = ks * 8;                                                \
                unsigned af[2][4];                                                    \
                _Pragma("unroll")                                                     \
                for (int mi = 0; mi < 2; mi++) {                                      \
                    const int mb = wrow + mi * 16;                                    \
                    af[mi][0] = __float_as_uint(As[st][mb + grp    ][kk + tig    ]);  \
                    af[mi][1] = __float_as_uint(As[st][mb + grp + 8][kk + tig    ]);  \
                    af[mi][2] = __float_as_uint(As[st][mb + grp    ][kk + tig + 4]);  \
                    af[mi][3] = __float_as_uint(As[st][mb + grp + 8][kk + tig + 4]);  \
                }                                                                     \
                _Pragma("unroll")                                                     \
                for (int nj = 0; nj < 8; nj++) {                                      \
                    const int nb = wcol + nj * 8;                                     \
                    unsigned b0 = __float_as_uint(Bs[st][kk + tig    ][nb + grp]);    \
                    unsigned b1 = __float_as_uint(Bs[st][kk + tig + 4][nb + grp]);    \
                    mma_tf32(acc[0][nj], af[0][0], af[0][1], af[0][2], af[0][3], b0, b1); \
                    mma_tf32(acc[1][nj], af[1][0], af[1][1], af[1][2], af[1][3], b0, b1); \
                }                                                                     \
            }                                                                         \
            asm volatile("cp.async.wait_group %0;" :: "n"(STG - 2));                  \
            __syncthreads();                                                          \
        } while (0)

    LOAD_STAGE(0,  0);
    LOAD_STAGE(16, 1);
    LOAD_STAGE(32, 2);
    LOAD_STAGE(48, 3);
    asm volatile("cp.async.wait_group %0;" :: "n"(STG - 2));
    __syncthreads();

    int it = 0;
    for (; it + STG <= NITER; it += STG) {
        ITER_BODY(0, it + 0);
        ITER_BODY(1, it + 1);
        ITER_BODY(2, it + 2);
        ITER_BODY(3, it + 3);
        ITER_BODY(4, it + 4);
    }
    if (NITER % STG > 0) ITER_BODY(0, (NITER / STG) * STG + 0);
    if (NITER % STG > 1) ITER_BODY(1, (NITER / STG) * STG + 1);
    if (NITER % STG > 2) ITER_BODY(2, (NITER / STG) * STG + 2);
    if (NITER % STG > 3) ITER_BODY(3, (NITER / STG) * STG + 3);

    #undef ITER_BODY
    #undef LOAD_STAGE

    // ---- epilogue ----
    #pragma unroll
    for (int mi = 0; mi < 2; mi++) {
        #pragma unroll
        for (int half = 0; half < 2; half++) {
            const int ml = mt * 128 + wrow + mi * 16 + grp + 8 * half;
            if (ml >= Me) continue;
            const int pos = m0 + ml;
            #pragma unroll
            for (int nj = 0; nj < 8; nj++) {
                const int col = wcol + nj * 8 + 2 * tig;
                float v0 = acc[mi][nj][2 * half];
                float v1 = acc[mi][nj][2 * half + 1];
                if (IS_FF1) {
                    const float* bia = bias + (size_t)e * N + nt * 128;
                    float2 o;
                    o.x = __uint_as_float(f2tf32(gelu_exact(v0 + bia[col])));
                    o.y = __uint_as_float(f2tf32(gelu_exact(v1 + bia[col + 1])));
                    *(float2*)&g_hbuf[(size_t)pos * N + (size_t)nt * 128 + col] = o;
                } else {
                    float2 o; o.x = v0; o.y = v1;
                    *(float2*)&g_part[(size_t)kc * Tn * N + (size_t)pos * N + (size_t)nt * 128 + col] = o;
                }
            }
        }
    }
}

// ============================================================
// FF2 reduce: sum split-K partials + bias + residual, scatter to out
// ============================================================
__global__ __launch_bounds__(256) void ff2_reduce(
    const float* __restrict__ b2, float* __restrict__ out)
{
    const int idx = blockIdx.x * 256 + threadIdx.x;   // float4 index
    if (idx >= Tn * Dm / 4) return;
    const int pos = idx / (Dm / 4);
    const int c   = (idx % (Dm / 4)) * 4;
    const int tok = g_perm[pos];
    const int e   = g_top1[tok];

    float4 s = *(const float4*)&g_part[(size_t)pos * Dm + c];
    #pragma unroll
    for (int kc = 1; kc < KSP2; kc++) {
        float4 p = *(const float4*)&g_part[(size_t)kc * Tn * Dm + (size_t)pos * Dm + c];
        s.x += p.x; s.y += p.y; s.z += p.z; s.w += p.w;
    }
    float4 bb = *(const float4*)&b2[(size_t)e * Dm + c];
    float4 xr = *(const float4*)&g_x1[(size_t)tok * Dm + c];
    s.x += bb.x + xr.x; s.y += bb.y + xr.y; s.z += bb.z + xr.z; s.w += bb.w + xr.w;
    *(float4*)&out[(size_t)tok * Dm + c] = s;
}

// ============================================================
extern "C" void kernel_launch(void* const* d_in, const int* in_sizes, int n_in,
                              void* d_out, int out_size)
{
    const float* x    = (const float*)d_in[0];
    const float* ln1g = (const float*)d_in[1];
    const float* ln1b = (const float*)d_in[2];
    // d_in[3..6] = Wq,bq,Wk,bk — provably unused (attention collapses to v)
    const float* Wv   = (const float*)d_in[7];
    const float* bv   = (const float*)d_in[8];
    const float* ln2g = (const float*)d_in[9];
    const float* ln2b = (const float*)d_in[10];
    const float* Wg   = (const float*)d_in[11];
    const float* bg   = (const float*)d_in[12];
    const float* W1   = (const float*)d_in[13];
    const float* b1   = (const float*)d_in[14];
    const float* W2   = (const float*)d_in[15];
    const float* b2   = (const float*)d_in[16];
    float* out = (float*)d_out;

    // idempotent, host-side, not a stream op — safe under graph capture.
    cudaFuncSetAttribute(moe_gemm_cp<Dm, FFd, true, 1>,
                         cudaFuncAttributeMaxDynamicSharedMemorySize, GEMM_SMEM_BYTES);
    cudaFuncSetAttribute(moe_gemm_cp<FFd, Dm, false, KSP2>,
                         cudaFuncAttributeMaxDynamicSharedMemorySize, GEMM_SMEM_BYTES);

    prep_kernel<<<Tn / 4, 256>>>(x, ln1g, ln1b, Wv, bv, ln2g, ln2b, Wg, bg);
    bucket_kernel<<<1, 1024>>>();
    moe_gemm_cp<Dm, FFd, true, 1>
        <<<dim3(FFd / 128, 13, NEx), 256, GEMM_SMEM_BYTES>>>(W1, b1);
    moe_gemm_cp<FFd, Dm, false, KSP2>
        <<<dim3(Dm / 128, 13, NEx * KSP2), 256, GEMM_SMEM_BYTES>>>(W2, nullptr);
    ff2_reduce<<<(Tn * Dm / 4 + 255) / 256, 256>>>(b2, out);
}

// round 13
// speedup vs baseline: 1.0641x; 1.0641x over previous
#include <cuda_runtime.h>
#include <cstdint>
#include <math.h>

#define Tn   1568
#define Dm   768
#define FFd  3072
#define NEx  8
#define HDh  64
#define KSP2 3          // split-K factor for FF2 (288 CTAs ~= one full wave)
#define STG  5          // cp.async pipeline stages (4 groups in flight)
#define NT1  96         // FF1 tile N (512 CTAs -> fuller waves)

// ---- scratch (allocation-free: __device__ globals) ----
__device__ float g_x1[Tn * Dm];            // residual after attention
__device__ float g_h2[Tn * Dm];            // LN2 output, tf32-rounded (MoE GEMM A)
__device__ float g_hbuf[Tn * FFd];         // FF1 activations, tf32-rounded, compact
__device__ float g_part[KSP2 * Tn * Dm];   // FF2 split-K partials
__device__ int   g_top1[Tn];
__device__ int   g_perm[Tn];
__device__ int   g_off[NEx + 1];

__device__ __forceinline__ unsigned f2tf32(float f) {
    unsigned r;
    asm("cvt.rna.tf32.f32 %0, %1;" : "=r"(r) : "f"(f));
    return r;
}

// ============================================================
// Kernel 1: LN1 + v-projection + residual + LN2 + gating
// Attention collapses algebraically: out_head(h) = v for all h.
// (round-11 proven version)
// ============================================================
__global__ __launch_bounds__(256) void prep_kernel(
    const float* __restrict__ x,
    const float* __restrict__ ln1g, const float* __restrict__ ln1b,
    const float* __restrict__ Wv,   const float* __restrict__ bv,
    const float* __restrict__ ln2g, const float* __restrict__ ln2b,
    const float* __restrict__ Wg,   const float* __restrict__ bg)
{
    __shared__ float xs[4][Dm];
    __shared__ float hs[4][Dm];
    __shared__ float vs[4][HDh];
    __shared__ float red[16];

    const int tid  = threadIdx.x;
    const int base = blockIdx.x * 4;

    for (int t = 0; t < 4; t++) {
        const float* xr = x + (size_t)(base + t) * Dm;
        float s = 0.f, ss = 0.f, lv[3];
        #pragma unroll
        for (int i = 0; i < 3; i++) {
            int c = tid + i * 256;
            float v = xr[c];
            lv[i] = v; xs[t][c] = v; s += v; ss += v * v;
        }
        #pragma unroll
        for (int o = 16; o; o >>= 1) {
            s  += __shfl_xor_sync(0xffffffffu, s,  o);
            ss += __shfl_xor_sync(0xffffffffu, ss, o);
        }
        if ((tid & 31) == 0) { red[tid >> 5] = s; red[8 + (tid >> 5)] = ss; }
        __syncthreads();
        s = 0.f; ss = 0.f;
        #pragma unroll
        for (int i = 0; i < 8; i++) { s += red[i]; ss += red[8 + i]; }
        float mu   = s * (1.f / Dm);
        float var  = ss * (1.f / Dm) - mu * mu;
        float rstd = rsqrtf(var + 1e-5f);
        #pragma unroll
        for (int i = 0; i < 3; i++) {
            int c = tid + i * 256;
            hs[t][c] = (lv[i] - mu) * rstd * ln1g[c] + ln1b[c];
        }
        __syncthreads();
    }

    {   // v = LN1(x) @ Wv + bv
        const int t2 = tid >> 6, j = tid & 63;
        float a0 = 0.f, a1 = 0.f, a2 = 0.f, a3 = 0.f;
        for (int k = 0; k < Dm; k += 4) {
            a0 += hs[t2][k + 0] * Wv[(k + 0) * HDh + j];
            a1 += hs[t2][k + 1] * Wv[(k + 1) * HDh + j];
            a2 += hs[t2][k + 2] * Wv[(k + 2) * HDh + j];
            a3 += hs[t2][k + 3] * Wv[(k + 3) * HDh + j];
        }
        vs[t2][j] = (a0 + a1) + (a2 + a3) + bv[j];
    }
    __syncthreads();

    for (int t = 0; t < 4; t++) {   // residual + LN2
        const int tok = base + t;
        float s = 0.f, ss = 0.f, lv[3];
        #pragma unroll
        for (int i = 0; i < 3; i++) {
            int c = tid + i * 256;
            float v = xs[t][c] + vs[t][c & (HDh - 1)];
            lv[i] = v; s += v; ss += v * v;
            g_x1[(size_t)tok * Dm + c] = v;
        }
        #pragma unroll
        for (int o = 16; o; o >>= 1) {
            s  += __shfl_xor_sync(0xffffffffu, s,  o);
            ss += __shfl_xor_sync(0xffffffffu, ss, o);
        }
        if ((tid & 31) == 0) { red[tid >> 5] = s; red[8 + (tid >> 5)] = ss; }
        __syncthreads();
        s = 0.f; ss = 0.f;
        #pragma unroll
        for (int i = 0; i < 8; i++) { s += red[i]; ss += red[8 + i]; }
        float mu   = s * (1.f / Dm);
        float var  = ss * (1.f / Dm) - mu * mu;
        float rstd = rsqrtf(var + 1e-5f);
        #pragma unroll
        for (int i = 0; i < 3; i++) {
            int c = tid + i * 256;
            float h = (lv[i] - mu) * rstd * ln2g[c] + ln2b[c];
            hs[t][c] = h;                                  // fp32 for gating
            g_h2[(size_t)tok * Dm + c] = __uint_as_float(f2tf32(h));  // tf32-rna for GEMM A
        }
        __syncthreads();
    }

    // gate logits + argmax (fp32)
    const int wid = tid >> 5, lane = tid & 31;
    if (wid < 4) {
        float lg[8];
        #pragma unroll
        for (int e = 0; e < 8; e++) lg[e] = 0.f;
        for (int k = lane; k < Dm; k += 32) {
            float h = hs[wid][k];
            #pragma unroll
            for (int e = 0; e < 8; e++) lg[e] += h * Wg[k * 8 + e];
        }
        #pragma unroll
        for (int e = 0; e < 8; e++)
            #pragma unroll
            for (int o = 16; o; o >>= 1) lg[e] += __shfl_xor_sync(0xffffffffu, lg[e], o);
        if (lane == 0) {
            float best = lg[0] + bg[0]; int bi = 0;
            #pragma unroll
            for (int e = 1; e < 8; e++) {
                float v = lg[e] + bg[e];
                if (v > best) { best = v; bi = e; }
            }
            g_top1[base + wid] = bi;
        }
    }
}

// ============================================================
// Kernel 2: bucket tokens by expert (single block)
// ============================================================
__global__ void bucket_kernel()
{
    __shared__ int cnt[NEx];
    __shared__ int cur[NEx];
    const int tid = threadIdx.x;
    if (tid < NEx) cnt[tid] = 0;
    __syncthreads();
    for (int i = tid; i < Tn; i += 256) atomicAdd(&cnt[g_top1[i]], 1);
    __syncthreads();
    if (tid == 0) {
        int acc = 0;
        for (int e = 0; e < NEx; e++) { g_off[e] = acc; cur[e] = acc; acc += cnt[e]; }
        g_off[NEx] = acc;
    }
    __syncthreads();
    for (int i = tid; i < Tn; i += 256) {
        int e = g_top1[i];
        int p = atomicAdd(&cur[e], 1);
        g_perm[p] = i;
    }
}

__device__ __forceinline__ float gelu_exact(float v) { return v * normcdff(v); }

__device__ __forceinline__ void mma_tf32(float* c,
    unsigned a0, unsigned a1, unsigned a2, unsigned a3,
    unsigned b0, unsigned b1)
{
    asm volatile(
        "mma.sync.aligned.m16n8k8.row.col.f32.tf32.tf32.f32 "
        "{%0,%1,%2,%3}, {%4,%5,%6,%7}, {%8,%9}, {%0,%1,%2,%3};"
        : "+f"(c[0]), "+f"(c[1]), "+f"(c[2]), "+f"(c[3])
        : "r"(a0), "r"(a1), "r"(a2), "r"(a3), "r"(b0), "r"(b1));
}

__device__ __forceinline__ uint32_t smem_u32(const void* p) {
    return (uint32_t)__cvta_generic_to_shared(p);
}
__device__ __forceinline__ void cp16(uint32_t dst, const void* src) {
    asm volatile("cp.async.cg.shared.global [%0], [%1], 16;" :: "r"(dst), "l"(src));
}
__device__ __forceinline__ void cp16z(uint32_t dst, const void* src, int sz) {
    asm volatile("cp.async.cg.shared.global [%0], [%1], 16, %2;" :: "r"(dst), "l"(src), "r"(sz));
}

// ============================================================
// TF32 tensor-core MoE GEMM, cp.async 5-stage pipeline, BK=16,
// static stage indices.  Block tile 128xNT (NT=128 or 96),
// 8 warps as 4M x 2N (warp tile 32 x NT/2).
// A smem [128][20]; B smem [16][NT+8]  (NT+8 = 8 mod 32 ->
// conflict-free frag loads, same bank pattern as the proven 136).
// NT=128 instantiation is bit-identical to the round-11 kernel.
// ============================================================
#define LDAA 20
#define GEMM_SMEM_BYTES(NT) ((STG * 128 * LDAA + STG * 16 * ((NT) + 8)) * 4)

template<int K, int N, int NT, bool IS_FF1, int KSPLIT>
__global__ __launch_bounds__(256, 2) void moe_gemm_cp(
    const float* __restrict__ W, const float* __restrict__ bias)
{
    const int e  = blockIdx.z / KSPLIT;
    const int kc = blockIdx.z % KSPLIT;
    constexpr int KS    = K / KSPLIT;
    constexpr int NITER = KS / 16;
    constexpr int LDBB  = NT + 8;
    constexpr int NJ    = NT / 16;       // n-subtiles per warp
    constexpr int BQ4   = NT / 4;        // float4s per B row
    static_assert(NITER >= STG, "pipeline deeper than loop");
    static_assert(NITER % STG <= 4, "peel covers at most 4");

    const int m0 = g_off[e];
    const int Me = g_off[e + 1] - m0;
    const int mt = blockIdx.y;
    if (mt * 128 >= Me) return;
    const int nt = blockIdx.x;

    extern __shared__ float smem[];
    float (*As)[128][LDAA] = (float (*)[128][LDAA])smem;
    float (*Bs)[16][LDBB]  = (float (*)[16][LDBB])(smem + STG * 128 * LDAA);

    const int tid  = threadIdx.x;
    const int lane = tid & 31;
    const int w    = tid >> 5;
    const int grp  = lane >> 2, tig = lane & 3;
    const int wrow = (w & 3) * 32;
    const int wcol = (w >> 2) * (NT / 2);

    // ---- A loader: rows ar0, ar0+64; k-quad akq ----
    const int ar0 = tid >> 2;
    const int akq = (tid & 3) * 4;
    // ---- B loader: j-th float4 of the 16 x NT stage, j in {tid, tid+256} ----
    const int  brow0 = tid / BQ4;
    const int  bcol0 = (tid % BQ4) * 4;
    const int  bi1   = tid + 256;
    const bool bv1   = bi1 < 4 * NT;     // 16*NT/4 float4s total
    const int  brow1 = bi1 / BQ4;
    const int  bcol1 = (bi1 % BQ4) * 4;

    const float* arowp[2]; int asz[2];
    #pragma unroll
    for (int i = 0; i < 2; i++) {
        int  mloc = mt * 128 + ar0 + i * 64;
        bool v    = mloc < Me;
        int  apos = m0 + (v ? mloc : 0);
        arowp[i] = (IS_FF1 ? &g_h2[(size_t)g_perm[apos] * K] : &g_hbuf[(size_t)apos * K])
                   + kc * KS + akq;
        asz[i] = v ? 16 : 0;
    }
    const float* __restrict__ Bb =
        W + (size_t)e * K * N + (size_t)(kc * KS) * N + (size_t)nt * NT;

    #define LOAD_STAGE(k0, st)                                                          \
        do {                                                                            \
            cp16z(smem_u32(&As[st][ar0][akq]),      arowp[0] + (k0), asz[0]);           \
            cp16z(smem_u32(&As[st][ar0 + 64][akq]), arowp[1] + (k0), asz[1]);           \
            cp16(smem_u32(&Bs[st][brow0][bcol0]), Bb + (size_t)((k0) + brow0) * N + bcol0); \
            if (bv1)                                                                    \
                cp16(smem_u32(&Bs[st][brow1][bcol1]), Bb + (size_t)((k0) + brow1) * N + bcol1); \
            asm volatile("cp.async.commit_group;");                                     \
        } while (0)

    float acc[2][NJ][4];
    #pragma unroll
    for (int i = 0; i < 2; i++)
        #pragma unroll
        for (int j = 0; j < NJ; j++)
            #pragma unroll
            for (int r = 0; r < 4; r++) acc[i][j][r] = 0.f;

    #define ITER_BODY(st, kit)                                                        \
        do {                                                                          \
            if ((kit) + STG - 1 < NITER) {                                            \
                LOAD_STAGE(((kit) + STG - 1) * 16, ((st) + STG - 1) % STG);           \
            } else {                                                                  \
                asm volatile("cp.async.commit_group;");                               \
            }                                                                         \
            _Pragma("unroll")                                                         \
            for (int ks = 0; ks < 2; ks++) {                                          \
                const int kk = ks * 8;                                                \
                unsigned af[2][4];                                                    \
                _Pragma("unroll")                                                     \
                for (int mi = 0; mi < 2; mi++) {                                      \
                    const int mb = wrow + mi * 16;                                    \
                    af[mi][0] = __float_as_uint(As[st][mb + grp    ][kk + tig    ]);  \
                    af[mi][1] = __float_as_uint(As[st][mb + grp + 8][kk + tig    ]);  \
                    af[mi][2] = __float_as_uint(As[st][mb + grp    ][kk + tig + 4]);  \
                    af[mi][3] = __float_as_uint(As[st][mb + grp + 8][kk + tig + 4]);  \
                }                                                                     \
                _Pragma("unroll")                                                     \
                for (int nj = 0; nj < NJ; nj++) {                                     \
                    const int nb = wcol + nj * 8;                                     \
                    unsigned b0 = __float_as_uint(Bs[st][kk + tig    ][nb + grp]);    \
                    unsigned b1 = __float_as_uint(Bs[st][kk + tig + 4][nb + grp]);    \
                    mma_tf32(acc[0][nj], af[0][0], af[0][1], af[0][2], af[0][3], b0, b1); \
                    mma_tf32(acc[1][nj], af[1][0], af[1][1], af[1][2], af[1][3], b0, b1); \
                }                                                                     \
            }                                                                         \
            asm volatile("cp.async.wait_group %0;" :: "n"(STG - 2));                  \
            __syncthreads();                                                          \
        } while (0)

    LOAD_STAGE(0,  0);
    LOAD_STAGE(16, 1);
    LOAD_STAGE(32, 2);
    LOAD_STAGE(48, 3);
    asm volatile("cp.async.wait_group %0;" :: "n"(STG - 2));
    __syncthreads();

    int it = 0;
    for (; it + STG <= NITER; it += STG) {
        ITER_BODY(0, it + 0);
        ITER_BODY(1, it + 1);
        ITER_BODY(2, it + 2);
        ITER_BODY(3, it + 3);
        ITER_BODY(4, it + 4);
    }
    if (NITER % STG > 0) ITER_BODY(0, (NITER / STG) * STG + 0);
    if (NITER % STG > 1) ITER_BODY(1, (NITER / STG) * STG + 1);
    if (NITER % STG > 2) ITER_BODY(2, (NITER / STG) * STG + 2);
    if (NITER % STG > 3) ITER_BODY(3, (NITER / STG) * STG + 3);

    #undef ITER_BODY
    #undef LOAD_STAGE

    // ---- epilogue ----
    // element (mi, nj, reg): row = wrow + mi*16 + grp + 8*(reg>>1)
    //                        col = wcol + nj*8 + 2*tig + (reg&1)
    #pragma unroll
    for (int mi = 0; mi < 2; mi++) {
        #pragma unroll
        for (int half = 0; half < 2; half++) {
            const int ml = mt * 128 + wrow + mi * 16 + grp + 8 * half;
            if (ml >= Me) continue;
            const int pos = m0 + ml;
            #pragma unroll
            for (int nj = 0; nj < NJ; nj++) {
                const int col = wcol + nj * 8 + 2 * tig;
                float v0 = acc[mi][nj][2 * half];
                float v1 = acc[mi][nj][2 * half + 1];
                if (IS_FF1) {
                    const float* bia = bias + (size_t)e * N + nt * NT;
                    float2 o;
                    o.x = __uint_as_float(f2tf32(gelu_exact(v0 + bia[col])));
                    o.y = __uint_as_float(f2tf32(gelu_exact(v1 + bia[col + 1])));
                    *(float2*)&g_hbuf[(size_t)pos * N + (size_t)nt * NT + col] = o;
                } else {
                    float2 o; o.x = v0; o.y = v1;
                    *(float2*)&g_part[(size_t)kc * Tn * N + (size_t)pos * N + (size_t)nt * NT + col] = o;
                }
            }
        }
    }
}

// ============================================================
// FF2 reduce: sum split-K partials + bias + residual, scatter to out
// ============================================================
__global__ __launch_bounds__(256) void ff2_reduce(
    const float* __restrict__ b2, float* __restrict__ out)
{
    const int idx = blockIdx.x * 256 + threadIdx.x;   // float4 index
    if (idx >= Tn * Dm / 4) return;
    const int pos = idx / (Dm / 4);
    const int c   = (idx % (Dm / 4)) * 4;
    const int tok = g_perm[pos];
    const int e   = g_top1[tok];

    float4 s = *(const float4*)&g_part[(size_t)pos * Dm + c];
    #pragma unroll
    for (int kc = 1; kc < KSP2; kc++) {
        float4 p = *(const float4*)&g_part[(size_t)kc * Tn * Dm + (size_t)pos * Dm + c];
        s.x += p.x; s.y += p.y; s.z += p.z; s.w += p.w;
    }
    float4 bb = *(const float4*)&b2[(size_t)e * Dm + c];
    float4 xr = *(const float4*)&g_x1[(size_t)tok * Dm + c];
    s.x += bb.x + xr.x; s.y += bb.y + xr.y; s.z += bb.z + xr.z; s.w += bb.w + xr.w;
    *(float4*)&out[(size_t)tok * Dm + c] = s;
}

// ============================================================
extern "C" void kernel_launch(void* const* d_in, const int* in_sizes, int n_in,
                              void* d_out, int out_size)
{
    const float* x    = (const float*)d_in[0];
    const float* ln1g = (const float*)d_in[1];
    const float* ln1b = (const float*)d_in[2];
    // d_in[3..6] = Wq,bq,Wk,bk — provably unused (attention collapses to v)
    const float* Wv   = (const float*)d_in[7];
    const float* bv   = (const float*)d_in[8];
    const float* ln2g = (const float*)d_in[9];
    const float* ln2b = (const float*)d_in[10];
    const float* Wg   = (const float*)d_in[11];
    const float* bg   = (const float*)d_in[12];
    const float* W1   = (const float*)d_in[13];
    const float* b1   = (const float*)d_in[14];
    const float* W2   = (const float*)d_in[15];
    const float* b2   = (const float*)d_in[16];
    float* out = (float*)d_out;

    // idempotent, host-side, not a stream op — safe under graph capture.
    cudaFuncSetAttribute(moe_gemm_cp<Dm, FFd, NT1, true, 1>,
                         cudaFuncAttributeMaxDynamicSharedMemorySize, GEMM_SMEM_BYTES(NT1));
    cudaFuncSetAttribute(moe_gemm_cp<FFd, Dm, 128, false, KSP2>,
                         cudaFuncAttributeMaxDynamicSharedMemorySize, GEMM_SMEM_BYTES(128));

    prep_kernel<<<Tn / 4, 256>>>(x, ln1g, ln1b, Wv, bv, ln2g, ln2b, Wg, bg);
    bucket_kernel<<<1, 256>>>();
    moe_gemm_cp<Dm, FFd, NT1, true, 1>
        <<<dim3(FFd / NT1, 13, NEx), 256, GEMM_SMEM_BYTES(NT1)>>>(W1, b1);
    moe_gemm_cp<FFd, Dm, 128, false, KSP2>
        <<<dim3(Dm / 128, 13, NEx * KSP2), 256, GEMM_SMEM_BYTES(128)>>>(W2, nullptr);
    ff2_reduce<<<(Tn * Dm / 4 + 255) / 256, 256>>>(b2, out);
}